// round 6
// baseline (speedup 1.0000x reference)
#include <cuda_runtime.h>
#include <cuda_fp16.h>
#include <cuda_bf16.h>
#include <cstdint>

// ---------------------------------------------------------------------------
// RelKDAdapter on GB300 (legacy-PTX target -> mma.sync path):
//   src_proj = x_src @ W_src   (fp16-input tensor-core GEMM, fp32 accum)
//   deg      = max(#edges per dst, 1)
//   dst      = segment-mean of src_proj[edge_col] over edge_row  (CSR gather)
// R6: GEMM epilogue additionally writes an fp16 shadow of src_proj; the
//     aggregation gathers the shadow (256B/row instead of 512B) -> halves
//     the L2 gather traffic. Accumulation stays fp32.
// ---------------------------------------------------------------------------

#define DD_SRC   256
#define DD_DST   64
#define DD_REL   128
#define MAX_NSRC 100000
#define MAX_NDST 100000
#define MAX_E    640000
#define SCAN_B   1024
#define MAX_SCAN_BLOCKS 128

__device__ int g_deg[MAX_NDST];
__device__ int g_rowptr[MAX_NDST + 1];
__device__ int g_cursor[MAX_NDST];
__device__ int g_cols[MAX_E];
__device__ int g_blksums[MAX_SCAN_BLOCKS];
__device__ __half g_Bh[DD_REL * DD_SRC];            // W^T, fp16: [128 n][256 k]
__device__ __half g_proj_h[(size_t)MAX_NSRC * DD_REL];  // fp16 shadow of src_proj

// ===========================================================================
// CSR build
// ===========================================================================
__global__ void k_zero_deg(int n) {
    int i = blockIdx.x * blockDim.x + threadIdx.x;
    if (i < n) g_deg[i] = 0;
}
__global__ void k_count(const int* __restrict__ erow, int E) {
    int e = blockIdx.x * blockDim.x + threadIdx.x;
    if (e < E) atomicAdd(&g_deg[erow[e]], 1);
}
__global__ void k_scan_partial(int n) {
    __shared__ int sh[SCAN_B];
    int i = blockIdx.x * SCAN_B + threadIdx.x;
    int v = (i < n) ? g_deg[i] : 0;
    sh[threadIdx.x] = v;
    __syncthreads();
#pragma unroll
    for (int off = 1; off < SCAN_B; off <<= 1) {
        int t = (threadIdx.x >= off) ? sh[threadIdx.x - off] : 0;
        __syncthreads();
        sh[threadIdx.x] += t;
        __syncthreads();
    }
    if (i < n) g_rowptr[i] = sh[threadIdx.x] - v;
    if (threadIdx.x == SCAN_B - 1) g_blksums[blockIdx.x] = sh[SCAN_B - 1];
}
__global__ void k_scan_add(int n, int E) {
    __shared__ int wsum[32];
    __shared__ int total;
    int lane = threadIdx.x & 31, wid = threadIdx.x >> 5;
    int local = 0;
    for (int j = threadIdx.x; j < blockIdx.x; j += blockDim.x) local += g_blksums[j];
#pragma unroll
    for (int o = 16; o > 0; o >>= 1) local += __shfl_down_sync(0xffffffffu, local, o);
    if (lane == 0) wsum[wid] = local;
    __syncthreads();
    if (wid == 0) {
        int s = (lane < (int)(blockDim.x >> 5)) ? wsum[lane] : 0;
#pragma unroll
        for (int o = 16; o > 0; o >>= 1) s += __shfl_down_sync(0xffffffffu, s, o);
        if (lane == 0) total = s;
    }
    __syncthreads();
    int i = blockIdx.x * SCAN_B + threadIdx.x;
    if (i < n) {
        int v = g_rowptr[i] + total;
        g_rowptr[i] = v;
        g_cursor[i] = v;
    }
    if (blockIdx.x == 0 && threadIdx.x == 0) g_rowptr[n] = E;
}
__global__ void k_fill(const int* __restrict__ erow, const int* __restrict__ ecol, int E) {
    int e = blockIdx.x * blockDim.x + threadIdx.x;
    if (e < E) {
        int r = erow[e];
        int p = atomicAdd(&g_cursor[r], 1);
        g_cols[p] = ecol[e];
    }
}

// ===========================================================================
// B transpose + fp16 convert: g_Bh[n][k] = half(W[k][n]);  W is [256][128]
// ===========================================================================
__global__ void k_transB(const float* __restrict__ W) {
    int i = blockIdx.x * 256 + threadIdx.x;
    if (i < DD_REL * DD_SRC) {
        int n = i >> 8;
        int k = i & 255;
        g_Bh[i] = __float2half_rn(W[k * DD_REL + n]);
    }
}

// ===========================================================================
// fp16 tensor-core GEMM: C[M,128] = A[M,256] @ Bh^T, fp32 accumulate.
// Bh staged fully in smem, 528B row stride -> conflict-free fragment LDS.
// 512 threads = 16 warps; warp tile 32x64; BM = 256; m16n8k16 HMMA.
// Epilogue: fp32 C + fp16 shadow g_proj_h.
// ===========================================================================
#define GEMM_BM 256
#define BROW    528
#define SMEM_SZ (128 * BROW)

__device__ __forceinline__ uint32_t pack_h2(float x, float y) {
    __half2 h = __floats2half2_rn(x, y);
    return *(uint32_t*)&h;
}

__global__ __launch_bounds__(512, 1)
void k_gemm_f16(const float* __restrict__ A, float* __restrict__ C, int M) {
    extern __shared__ char smemc[];
    const int tid = threadIdx.x;

    // ---- stage Bh into smem via cp.async ----
    {
        const char* src_base = (const char*)g_Bh;
#pragma unroll
        for (int t = 0; t < 8; t++) {
            int i = tid + t * 512;
            int n = i >> 5;
            int q = i & 31;
            uint32_t dst;
            asm("{ .reg .u64 tt; cvta.to.shared.u64 tt, %1; cvt.u32.u64 %0, tt; }"
                : "=r"(dst) : "l"(smemc + n * BROW + q * 16));
            const char* src = src_base + (size_t)n * 512 + q * 16;
            asm volatile("cp.async.cg.shared.global [%0], [%1], 16;" :: "r"(dst), "l"(src));
        }
        asm volatile("cp.async.commit_group;" ::: "memory");
        asm volatile("cp.async.wait_group 0;" ::: "memory");
    }
    __syncthreads();

    const int warp = tid >> 5;
    const int lane = tid & 31;
    const int gid  = lane >> 2;
    const int tig  = lane & 3;
    const int wm   = warp >> 1;
    const int wn   = warp & 1;

    const int row0 = blockIdx.x * GEMM_BM + wm * 32;
    const int rA = row0 + gid;
    const int rB = row0 + 16 + gid;
    const bool okA  = (rA      < M);
    const bool okA8 = (rA + 8  < M);
    const bool okB  = (rB      < M);
    const bool okB8 = (rB + 8  < M);

    const int cl = M - 1;
    const float* pA0 = A + (size_t)(okA  ? rA     : cl) * DD_SRC;
    const float* pA1 = A + (size_t)(okA8 ? rA + 8 : cl) * DD_SRC;
    const float* pB0 = A + (size_t)(okB  ? rB     : cl) * DD_SRC;
    const float* pB1 = A + (size_t)(okB8 ? rB + 8 : cl) * DD_SRC;

    const char* bbase = smemc + (wn * 64 + gid) * BROW + tig * 4;

    float c0[8][4], c1[8][4];
#pragma unroll
    for (int nt = 0; nt < 8; nt++)
#pragma unroll
        for (int j = 0; j < 4; j++) { c0[nt][j] = 0.f; c1[nt][j] = 0.f; }

#pragma unroll 2
    for (int ks = 0; ks < 16; ks++) {
        const int k0 = ks * 16;
        const int kk = k0 + 2 * tig;

        float2 vA0  = __ldg((const float2*)(pA0 + kk));
        float2 vA0b = __ldg((const float2*)(pA0 + kk + 8));
        float2 vA1  = __ldg((const float2*)(pA1 + kk));
        float2 vA1b = __ldg((const float2*)(pA1 + kk + 8));
        float2 vB0  = __ldg((const float2*)(pB0 + kk));
        float2 vB0b = __ldg((const float2*)(pB0 + kk + 8));
        float2 vB1  = __ldg((const float2*)(pB1 + kk));
        float2 vB1b = __ldg((const float2*)(pB1 + kk + 8));

        uint32_t a00 = pack_h2(vA0.x,  vA0.y);
        uint32_t a01 = pack_h2(vA1.x,  vA1.y);
        uint32_t a02 = pack_h2(vA0b.x, vA0b.y);
        uint32_t a03 = pack_h2(vA1b.x, vA1b.y);
        uint32_t a10 = pack_h2(vB0.x,  vB0.y);
        uint32_t a11 = pack_h2(vB1.x,  vB1.y);
        uint32_t a12 = pack_h2(vB0b.x, vB0b.y);
        uint32_t a13 = pack_h2(vB1b.x, vB1b.y);

        const char* bk = bbase + k0 * 2;
#pragma unroll
        for (int nt = 0; nt < 8; nt++) {
            uint32_t b0 = *(const uint32_t*)(bk + nt * (8 * BROW));
            uint32_t b1 = *(const uint32_t*)(bk + nt * (8 * BROW) + 16);
            asm volatile(
                "mma.sync.aligned.m16n8k16.row.col.f32.f16.f16.f32 "
                "{%0,%1,%2,%3}, {%4,%5,%6,%7}, {%8,%9}, {%0,%1,%2,%3};\n"
                : "+f"(c0[nt][0]), "+f"(c0[nt][1]), "+f"(c0[nt][2]), "+f"(c0[nt][3])
                : "r"(a00), "r"(a01), "r"(a02), "r"(a03), "r"(b0), "r"(b1));
            asm volatile(
                "mma.sync.aligned.m16n8k16.row.col.f32.f16.f16.f32 "
                "{%0,%1,%2,%3}, {%4,%5,%6,%7}, {%8,%9}, {%0,%1,%2,%3};\n"
                : "+f"(c1[nt][0]), "+f"(c1[nt][1]), "+f"(c1[nt][2]), "+f"(c1[nt][3])
                : "r"(a10), "r"(a11), "r"(a12), "r"(a13), "r"(b0), "r"(b1));
        }
    }

    // ---- epilogue: fp32 C + fp16 shadow ----
    __half* H = g_proj_h;
#pragma unroll
    for (int nt = 0; nt < 8; nt++) {
        int col = wn * 64 + nt * 8 + 2 * tig;
        if (okA) {
            *(float2*)(C + (size_t)rA * DD_REL + col) = make_float2(c0[nt][0], c0[nt][1]);
            *(uint32_t*)(H + (size_t)rA * DD_REL + col) = pack_h2(c0[nt][0], c0[nt][1]);
        }
        if (okA8) {
            *(float2*)(C + (size_t)(rA + 8) * DD_REL + col) = make_float2(c0[nt][2], c0[nt][3]);
            *(uint32_t*)(H + (size_t)(rA + 8) * DD_REL + col) = pack_h2(c0[nt][2], c0[nt][3]);
        }
        if (okB) {
            *(float2*)(C + (size_t)rB * DD_REL + col) = make_float2(c1[nt][0], c1[nt][1]);
            *(uint32_t*)(H + (size_t)rB * DD_REL + col) = pack_h2(c1[nt][0], c1[nt][1]);
        }
        if (okB8) {
            *(float2*)(C + (size_t)(rB + 8) * DD_REL + col) = make_float2(c1[nt][2], c1[nt][3]);
            *(uint32_t*)(H + (size_t)(rB + 8) * DD_REL + col) = pack_h2(c1[nt][2], c1[nt][3]);
        }
    }
}

// ===========================================================================
// aggregation: one warp per dst row; gathers the fp16 shadow (256B/row),
// lane owns 4 columns (uint2 = 4 halfs), fp32 accumulation, 4-edge unroll.
// ===========================================================================
__global__ void k_aggregate(float* __restrict__ dst_out,
                            float* __restrict__ deg_out,
                            int n_dst) {
    int gwarp = (blockIdx.x * blockDim.x + threadIdx.x) >> 5;
    int lane  = threadIdx.x & 31;
    if (gwarp >= n_dst) return;

    int beg = g_rowptr[gwarp];
    int end = g_rowptr[gwarp + 1];

    const uint2* hp = (const uint2*)g_proj_h;   // 4 halfs per uint2; 32/row
    float4 acc = make_float4(0.f, 0.f, 0.f, 0.f);

    int e = beg;
    for (; e + 4 <= end; e += 4) {
        int c0 = g_cols[e], c1 = g_cols[e + 1], c2 = g_cols[e + 2], c3 = g_cols[e + 3];
        uint2 u0 = __ldg(&hp[(size_t)c0 * 32 + lane]);
        uint2 u1 = __ldg(&hp[(size_t)c1 * 32 + lane]);
        uint2 u2 = __ldg(&hp[(size_t)c2 * 32 + lane]);
        uint2 u3 = __ldg(&hp[(size_t)c3 * 32 + lane]);
        float2 f0a = __half22float2(*(__half2*)&u0.x), f0b = __half22float2(*(__half2*)&u0.y);
        float2 f1a = __half22float2(*(__half2*)&u1.x), f1b = __half22float2(*(__half2*)&u1.y);
        float2 f2a = __half22float2(*(__half2*)&u2.x), f2b = __half22float2(*(__half2*)&u2.y);
        float2 f3a = __half22float2(*(__half2*)&u3.x), f3b = __half22float2(*(__half2*)&u3.y);
        acc.x += (f0a.x + f1a.x) + (f2a.x + f3a.x);
        acc.y += (f0a.y + f1a.y) + (f2a.y + f3a.y);
        acc.z += (f0b.x + f1b.x) + (f2b.x + f3b.x);
        acc.w += (f0b.y + f1b.y) + (f2b.y + f3b.y);
    }
    for (; e < end; e++) {
        int c0 = g_cols[e];
        uint2 u0 = __ldg(&hp[(size_t)c0 * 32 + lane]);
        float2 f0a = __half22float2(*(__half2*)&u0.x), f0b = __half22float2(*(__half2*)&u0.y);
        acc.x += f0a.x; acc.y += f0a.y; acc.z += f0b.x; acc.w += f0b.y;
    }

    float d = fmaxf((float)(end - beg), 1.f);
    float inv = 1.f / d;
    acc.x *= inv; acc.y *= inv; acc.z *= inv; acc.w *= inv;

    ((float4*)dst_out)[(size_t)gwarp * 32 + lane] = acc;
    if (lane == 0) deg_out[gwarp] = d;
}

// ===========================================================================
extern "C" void kernel_launch(void* const* d_in, const int* in_sizes, int n_in,
                              void* d_out, int out_size) {
    const float* x_src = (const float*)d_in[0];
    const float* W_src = (const float*)d_in[2];
    const int*   erow  = (const int*)d_in[4];
    const int*   ecol  = (const int*)d_in[5];

    const int N_src = in_sizes[0] / DD_SRC;
    const int N_dst = in_sizes[1] / DD_DST;
    const int E     = in_sizes[4];

    float* out         = (float*)d_out;
    float* dst_out     = out;
    float* srcproj_out = out + (size_t)N_dst * DD_REL;
    float* deg_out     = srcproj_out + (size_t)N_src * DD_REL;

    static cudaStream_t s_csr = nullptr;
    static cudaEvent_t  ev_fork = nullptr, ev_join = nullptr;
    static int init_done = 0;
    if (!init_done) {
        cudaFuncSetAttribute(k_gemm_f16,
                             cudaFuncAttributeMaxDynamicSharedMemorySize, SMEM_SZ);
        cudaStreamCreateWithFlags(&s_csr, cudaStreamNonBlocking);
        cudaEventCreateWithFlags(&ev_fork, cudaEventDisableTiming);
        cudaEventCreateWithFlags(&ev_join, cudaEventDisableTiming);
        init_done = 1;
    }

    cudaEventRecord(ev_fork, 0);
    cudaStreamWaitEvent(s_csr, ev_fork, 0);

    // --- CSR branch (side stream, overlaps transB + GEMM) ---
    k_zero_deg<<<(N_dst + 255) / 256, 256, 0, s_csr>>>(N_dst);
    k_count<<<(E + 255) / 256, 256, 0, s_csr>>>(erow, E);
    int nb = (N_dst + SCAN_B - 1) / SCAN_B;
    k_scan_partial<<<nb, SCAN_B, 0, s_csr>>>(N_dst);
    k_scan_add<<<nb, SCAN_B, 0, s_csr>>>(N_dst, E);
    k_fill<<<(E + 255) / 256, 256, 0, s_csr>>>(erow, ecol, E);
    cudaEventRecord(ev_join, s_csr);

    // --- main stream: B transpose->fp16, then GEMM ---
    k_transB<<<(DD_REL * DD_SRC + 255) / 256, 256>>>(W_src);
    int gm_blocks = (N_src + GEMM_BM - 1) / GEMM_BM;
    k_gemm_f16<<<gm_blocks, 512, SMEM_SZ>>>(x_src, srcproj_out, N_src);

    cudaStreamWaitEvent(0, ev_join, 0);

    // --- aggregation (gathers fp16 shadow) ---
    int agg_blocks = (N_dst + 7) / 8;
    k_aggregate<<<agg_blocks, 256>>>(dst_out, deg_out, N_dst);
}

// round 7
// speedup vs baseline: 1.0813x; 1.0813x over previous
#include <cuda_runtime.h>
#include <cuda_fp16.h>
#include <cuda_bf16.h>
#include <cstdint>

// ---------------------------------------------------------------------------
// RelKDAdapter on GB300 (legacy-PTX target -> mma.sync path):
//   src_proj = x_src @ W_src   (fp16-input tensor-core GEMM, fp32 accum)
//   deg      = max(#edges per dst, 1)
//   dst      = segment-mean of src_proj[edge_col] over edge_row  (CSR gather)
// R7: software-pipelined A loads in the GEMM (1-deep register prefetch);
//     agg back to fp32 gather (R5); submission order tuned so ncu profiles
//     the GEMM next round.
// ---------------------------------------------------------------------------

#define DD_SRC   256
#define DD_DST   64
#define DD_REL   128
#define MAX_NDST 100000
#define MAX_E    640000
#define SCAN_B   1024
#define MAX_SCAN_BLOCKS 128

__device__ int g_deg[MAX_NDST];
__device__ int g_rowptr[MAX_NDST + 1];
__device__ int g_cursor[MAX_NDST];
__device__ int g_cols[MAX_E];
__device__ int g_blksums[MAX_SCAN_BLOCKS];
__device__ __half g_Bh[DD_REL * DD_SRC];   // W^T fp16: [128 n][256 k]

// ===========================================================================
// CSR build
// ===========================================================================
__global__ void k_zero_deg(int n) {
    int i = blockIdx.x * blockDim.x + threadIdx.x;
    if (i < n) g_deg[i] = 0;
}
__global__ void k_count(const int* __restrict__ erow, int E) {
    int e = blockIdx.x * blockDim.x + threadIdx.x;
    if (e < E) atomicAdd(&g_deg[erow[e]], 1);
}
__global__ void k_scan_partial(int n) {
    __shared__ int sh[SCAN_B];
    int i = blockIdx.x * SCAN_B + threadIdx.x;
    int v = (i < n) ? g_deg[i] : 0;
    sh[threadIdx.x] = v;
    __syncthreads();
#pragma unroll
    for (int off = 1; off < SCAN_B; off <<= 1) {
        int t = (threadIdx.x >= off) ? sh[threadIdx.x - off] : 0;
        __syncthreads();
        sh[threadIdx.x] += t;
        __syncthreads();
    }
    if (i < n) g_rowptr[i] = sh[threadIdx.x] - v;
    if (threadIdx.x == SCAN_B - 1) g_blksums[blockIdx.x] = sh[SCAN_B - 1];
}
__global__ void k_scan_add(int n, int E) {
    __shared__ int wsum[32];
    __shared__ int total;
    int lane = threadIdx.x & 31, wid = threadIdx.x >> 5;
    int local = 0;
    for (int j = threadIdx.x; j < blockIdx.x; j += blockDim.x) local += g_blksums[j];
#pragma unroll
    for (int o = 16; o > 0; o >>= 1) local += __shfl_down_sync(0xffffffffu, local, o);
    if (lane == 0) wsum[wid] = local;
    __syncthreads();
    if (wid == 0) {
        int s = (lane < (int)(blockDim.x >> 5)) ? wsum[lane] : 0;
#pragma unroll
        for (int o = 16; o > 0; o >>= 1) s += __shfl_down_sync(0xffffffffu, s, o);
        if (lane == 0) total = s;
    }
    __syncthreads();
    int i = blockIdx.x * SCAN_B + threadIdx.x;
    if (i < n) {
        int v = g_rowptr[i] + total;
        g_rowptr[i] = v;
        g_cursor[i] = v;
    }
    if (blockIdx.x == 0 && threadIdx.x == 0) g_rowptr[n] = E;
}
__global__ void k_fill(const int* __restrict__ erow, const int* __restrict__ ecol, int E) {
    int e = blockIdx.x * blockDim.x + threadIdx.x;
    if (e < E) {
        int r = erow[e];
        int p = atomicAdd(&g_cursor[r], 1);
        g_cols[p] = ecol[e];
    }
}

// ===========================================================================
// B transpose + fp16 convert: g_Bh[n][k] = half(W[k][n]);  W is [256][128]
// ===========================================================================
__global__ void k_transB(const float* __restrict__ W) {
    int i = blockIdx.x * 256 + threadIdx.x;
    if (i < DD_REL * DD_SRC) {
        int n = i >> 8;
        int k = i & 255;
        g_Bh[i] = __float2half_rn(W[k * DD_REL + n]);
    }
}

// ===========================================================================
// fp16 tensor-core GEMM with software-pipelined A loads.
// C[M,128] = A[M,256] @ Bh^T, fp32 accumulate.
// Bh fully staged in smem (528B rows, conflict-free fragment LDS).
// 512 threads = 16 warps; warp tile 32x64; BM = 256; m16n8k16 HMMA.
// ===========================================================================
#define GEMM_BM 256
#define BROW    528
#define SMEM_SZ (128 * BROW)

__device__ __forceinline__ uint32_t pack_h2(float x, float y) {
    __half2 h = __floats2half2_rn(x, y);
    return *(uint32_t*)&h;
}

__global__ __launch_bounds__(512, 1)
void k_gemm_f16(const float* __restrict__ A, float* __restrict__ C, int M) {
    extern __shared__ char smemc[];
    const int tid = threadIdx.x;

    // ---- stage Bh into smem via cp.async ----
    {
        const char* src_base = (const char*)g_Bh;
#pragma unroll
        for (int t = 0; t < 8; t++) {
            int i = tid + t * 512;
            int n = i >> 5;
            int q = i & 31;
            uint32_t dst;
            asm("{ .reg .u64 tt; cvta.to.shared.u64 tt, %1; cvt.u32.u64 %0, tt; }"
                : "=r"(dst) : "l"(smemc + n * BROW + q * 16));
            const char* src = src_base + (size_t)n * 512 + q * 16;
            asm volatile("cp.async.cg.shared.global [%0], [%1], 16;" :: "r"(dst), "l"(src));
        }
        asm volatile("cp.async.commit_group;" ::: "memory");
        asm volatile("cp.async.wait_group 0;" ::: "memory");
    }
    __syncthreads();

    const int warp = tid >> 5;
    const int lane = tid & 31;
    const int gid  = lane >> 2;
    const int tig  = lane & 3;
    const int wm   = warp >> 1;
    const int wn   = warp & 1;

    const int row0 = blockIdx.x * GEMM_BM + wm * 32;
    const int rA = row0 + gid;
    const int rB = row0 + 16 + gid;
    const bool okA  = (rA      < M);
    const bool okA8 = (rA + 8  < M);
    const bool okB  = (rB      < M);
    const bool okB8 = (rB + 8  < M);

    const int cl = M - 1;
    const float* pA0 = A + (size_t)(okA  ? rA     : cl) * DD_SRC + 2 * tig;
    const float* pA1 = A + (size_t)(okA8 ? rA + 8 : cl) * DD_SRC + 2 * tig;
    const float* pB0 = A + (size_t)(okB  ? rB     : cl) * DD_SRC + 2 * tig;
    const float* pB1 = A + (size_t)(okB8 ? rB + 8 : cl) * DD_SRC + 2 * tig;

    const char* bbase = smemc + (wn * 64 + gid) * BROW + tig * 4;

    float c0[8][4], c1[8][4];
#pragma unroll
    for (int nt = 0; nt < 8; nt++)
#pragma unroll
        for (int j = 0; j < 4; j++) { c0[nt][j] = 0.f; c1[nt][j] = 0.f; }

    // ---- prefetch buffer (1-deep) ----
    float2 pf[8];
    pf[0] = __ldg((const float2*)(pA0));
    pf[1] = __ldg((const float2*)(pA0 + 8));
    pf[2] = __ldg((const float2*)(pA1));
    pf[3] = __ldg((const float2*)(pA1 + 8));
    pf[4] = __ldg((const float2*)(pB0));
    pf[5] = __ldg((const float2*)(pB0 + 8));
    pf[6] = __ldg((const float2*)(pB1));
    pf[7] = __ldg((const float2*)(pB1 + 8));

#pragma unroll
    for (int ks = 0; ks < 16; ks++) {
        // pack current a-fragments from prefetch buffer
        uint32_t a00 = pack_h2(pf[0].x, pf[0].y);
        uint32_t a02 = pack_h2(pf[1].x, pf[1].y);
        uint32_t a01 = pack_h2(pf[2].x, pf[2].y);
        uint32_t a03 = pack_h2(pf[3].x, pf[3].y);
        uint32_t a10 = pack_h2(pf[4].x, pf[4].y);
        uint32_t a12 = pack_h2(pf[5].x, pf[5].y);
        uint32_t a11 = pack_h2(pf[6].x, pf[6].y);
        uint32_t a13 = pack_h2(pf[7].x, pf[7].y);

        // issue next iteration's loads (latency covered by the mma block)
        if (ks < 15) {
            const int kn = (ks + 1) * 16;
            pf[0] = __ldg((const float2*)(pA0 + kn));
            pf[1] = __ldg((const float2*)(pA0 + kn + 8));
            pf[2] = __ldg((const float2*)(pA1 + kn));
            pf[3] = __ldg((const float2*)(pA1 + kn + 8));
            pf[4] = __ldg((const float2*)(pB0 + kn));
            pf[5] = __ldg((const float2*)(pB0 + kn + 8));
            pf[6] = __ldg((const float2*)(pB1 + kn));
            pf[7] = __ldg((const float2*)(pB1 + kn + 8));
        }

        const char* bk = bbase + ks * 32;   // k0*2 bytes
#pragma unroll
        for (int nt = 0; nt < 8; nt++) {
            uint32_t b0 = *(const uint32_t*)(bk + nt * (8 * BROW));
            uint32_t b1 = *(const uint32_t*)(bk + nt * (8 * BROW) + 16);
            asm volatile(
                "mma.sync.aligned.m16n8k16.row.col.f32.f16.f16.f32 "
                "{%0,%1,%2,%3}, {%4,%5,%6,%7}, {%8,%9}, {%0,%1,%2,%3};\n"
                : "+f"(c0[nt][0]), "+f"(c0[nt][1]), "+f"(c0[nt][2]), "+f"(c0[nt][3])
                : "r"(a00), "r"(a01), "r"(a02), "r"(a03), "r"(b0), "r"(b1));
            asm volatile(
                "mma.sync.aligned.m16n8k16.row.col.f32.f16.f16.f32 "
                "{%0,%1,%2,%3}, {%4,%5,%6,%7}, {%8,%9}, {%0,%1,%2,%3};\n"
                : "+f"(c1[nt][0]), "+f"(c1[nt][1]), "+f"(c1[nt][2]), "+f"(c1[nt][3])
                : "r"(a10), "r"(a11), "r"(a12), "r"(a13), "r"(b0), "r"(b1));
        }
    }

    // ---- store ----
#pragma unroll
    for (int nt = 0; nt < 8; nt++) {
        int col = wn * 64 + nt * 8 + 2 * tig;
        if (okA)  *(float2*)(C + (size_t)rA       * DD_REL + col) = make_float2(c0[nt][0], c0[nt][1]);
        if (okA8) *(float2*)(C + (size_t)(rA + 8) * DD_REL + col) = make_float2(c0[nt][2], c0[nt][3]);
        if (okB)  *(float2*)(C + (size_t)rB       * DD_REL + col) = make_float2(c1[nt][0], c1[nt][1]);
        if (okB8) *(float2*)(C + (size_t)(rB + 8) * DD_REL + col) = make_float2(c1[nt][2], c1[nt][3]);
    }
}

// ===========================================================================
// aggregation: one warp per dst row, float4 per lane, 4-way unrolled gather
// ===========================================================================
__global__ void k_aggregate(const float* __restrict__ src_proj,
                            float* __restrict__ dst_out,
                            float* __restrict__ deg_out,
                            int n_dst) {
    int gwarp = (blockIdx.x * blockDim.x + threadIdx.x) >> 5;
    int lane  = threadIdx.x & 31;
    if (gwarp >= n_dst) return;

    int beg = g_rowptr[gwarp];
    int end = g_rowptr[gwarp + 1];

    const float4* sp = (const float4*)src_proj;
    float4 acc = make_float4(0.f, 0.f, 0.f, 0.f);

    int e = beg;
    for (; e + 4 <= end; e += 4) {
        int c0 = g_cols[e], c1 = g_cols[e + 1], c2 = g_cols[e + 2], c3 = g_cols[e + 3];
        float4 v0 = __ldg(&sp[(size_t)c0 * 32 + lane]);
        float4 v1 = __ldg(&sp[(size_t)c1 * 32 + lane]);
        float4 v2 = __ldg(&sp[(size_t)c2 * 32 + lane]);
        float4 v3 = __ldg(&sp[(size_t)c3 * 32 + lane]);
        acc.x += (v0.x + v1.x) + (v2.x + v3.x);
        acc.y += (v0.y + v1.y) + (v2.y + v3.y);
        acc.z += (v0.z + v1.z) + (v2.z + v3.z);
        acc.w += (v0.w + v1.w) + (v2.w + v3.w);
    }
    for (; e < end; e++) {
        int c0 = g_cols[e];
        float4 v0 = __ldg(&sp[(size_t)c0 * 32 + lane]);
        acc.x += v0.x; acc.y += v0.y; acc.z += v0.z; acc.w += v0.w;
    }

    float d = fmaxf((float)(end - beg), 1.f);
    float inv = 1.f / d;
    acc.x *= inv; acc.y *= inv; acc.z *= inv; acc.w *= inv;

    ((float4*)dst_out)[(size_t)gwarp * 32 + lane] = acc;
    if (lane == 0) deg_out[gwarp] = d;
}

// ===========================================================================
extern "C" void kernel_launch(void* const* d_in, const int* in_sizes, int n_in,
                              void* d_out, int out_size) {
    const float* x_src = (const float*)d_in[0];
    const float* W_src = (const float*)d_in[2];
    const int*   erow  = (const int*)d_in[4];
    const int*   ecol  = (const int*)d_in[5];

    const int N_src = in_sizes[0] / DD_SRC;
    const int N_dst = in_sizes[1] / DD_DST;
    const int E     = in_sizes[4];

    float* out         = (float*)d_out;
    float* dst_out     = out;
    float* srcproj_out = out + (size_t)N_dst * DD_REL;
    float* deg_out     = srcproj_out + (size_t)N_src * DD_REL;

    static cudaStream_t s_csr = nullptr;
    static cudaEvent_t  ev_fork = nullptr, ev_join = nullptr;
    static int init_done = 0;
    if (!init_done) {
        cudaFuncSetAttribute(k_gemm_f16,
                             cudaFuncAttributeMaxDynamicSharedMemorySize, SMEM_SZ);
        cudaStreamCreateWithFlags(&s_csr, cudaStreamNonBlocking);
        cudaEventCreateWithFlags(&ev_fork, cudaEventDisableTiming);
        cudaEventCreateWithFlags(&ev_join, cudaEventDisableTiming);
        init_done = 1;
    }

    cudaEventRecord(ev_fork, 0);
    cudaStreamWaitEvent(s_csr, ev_fork, 0);

    // Submission order tuned so the GEMM is the 4th kernel submitted (ncu has
    // consistently profiled submission index 3). Execution order is stream-
    // ordered, so this does not change the schedule.
    k_zero_deg<<<(N_dst + 255) / 256, 256, 0, s_csr>>>(N_dst);            // idx 0
    k_count<<<(E + 255) / 256, 256, 0, s_csr>>>(erow, E);                 // idx 1
    k_transB<<<(DD_REL * DD_SRC + 255) / 256, 256>>>(W_src);              // idx 2
    int gm_blocks = (N_src + GEMM_BM - 1) / GEMM_BM;
    k_gemm_f16<<<gm_blocks, 512, SMEM_SZ>>>(x_src, srcproj_out, N_src);   // idx 3

    int nb = (N_dst + SCAN_B - 1) / SCAN_B;
    k_scan_partial<<<nb, SCAN_B, 0, s_csr>>>(N_dst);                      // idx 4
    k_scan_add<<<nb, SCAN_B, 0, s_csr>>>(N_dst, E);                       // idx 5
    k_fill<<<(E + 255) / 256, 256, 0, s_csr>>>(erow, ecol, E);            // idx 6
    cudaEventRecord(ev_join, s_csr);
    cudaStreamWaitEvent(0, ev_join, 0);

    // --- aggregation ---
    int agg_blocks = (N_dst + 7) / 8;
    k_aggregate<<<agg_blocks, 256>>>(srcproj_out, dst_out, deg_out, N_dst); // idx 7
}

// round 10
// speedup vs baseline: 1.0854x; 1.0038x over previous
#include <cuda_runtime.h>
#include <cuda_fp16.h>
#include <cuda_bf16.h>
#include <cstdint>

// ---------------------------------------------------------------------------
// RelKDAdapter on GB300 (legacy-PTX target -> mma.sync path):
//   src_proj = x_src @ W_src   (fp16-input tensor-core GEMM, fp32 accum)
//   deg      = max(#edges per dst, 1)
//   dst      = segment-mean of src_proj[edge_col] over edge_row  (CSR gather)
// R9: fixes R8's pipeline bug — the final K-chunk must use cp.async.wait_group 0
//     (A7's commit-group could still be in flight under wait_group 1).
// ---------------------------------------------------------------------------

#define DD_SRC   256
#define DD_DST   64
#define DD_REL   128
#define MAX_NDST 100000
#define MAX_E    640000
#define SCAN_B   1024
#define MAX_SCAN_BLOCKS 128

__device__ int g_deg[MAX_NDST];
__device__ int g_rowptr[MAX_NDST + 1];
__device__ int g_cursor[MAX_NDST];
__device__ int g_cols[MAX_E];
__device__ int g_blksums[MAX_SCAN_BLOCKS];
__device__ __half g_Bh[DD_REL * DD_SRC];   // W^T fp16: [128 n][256 k]

// ===========================================================================
// CSR build
// ===========================================================================
__global__ void k_zero_deg(int n) {
    int i = blockIdx.x * blockDim.x + threadIdx.x;
    if (i < n) g_deg[i] = 0;
}
__global__ void k_count(const int* __restrict__ erow, int E) {
    int e = blockIdx.x * blockDim.x + threadIdx.x;
    if (e < E) atomicAdd(&g_deg[erow[e]], 1);
}
__global__ void k_scan_partial(int n) {
    __shared__ int sh[SCAN_B];
    int i = blockIdx.x * SCAN_B + threadIdx.x;
    int v = (i < n) ? g_deg[i] : 0;
    sh[threadIdx.x] = v;
    __syncthreads();
#pragma unroll
    for (int off = 1; off < SCAN_B; off <<= 1) {
        int t = (threadIdx.x >= off) ? sh[threadIdx.x - off] : 0;
        __syncthreads();
        sh[threadIdx.x] += t;
        __syncthreads();
    }
    if (i < n) g_rowptr[i] = sh[threadIdx.x] - v;
    if (threadIdx.x == SCAN_B - 1) g_blksums[blockIdx.x] = sh[SCAN_B - 1];
}
__global__ void k_scan_add(int n, int E) {
    __shared__ int wsum[32];
    __shared__ int total;
    int lane = threadIdx.x & 31, wid = threadIdx.x >> 5;
    int local = 0;
    for (int j = threadIdx.x; j < blockIdx.x; j += blockDim.x) local += g_blksums[j];
#pragma unroll
    for (int o = 16; o > 0; o >>= 1) local += __shfl_down_sync(0xffffffffu, local, o);
    if (lane == 0) wsum[wid] = local;
    __syncthreads();
    if (wid == 0) {
        int s = (lane < (int)(blockDim.x >> 5)) ? wsum[lane] : 0;
#pragma unroll
        for (int o = 16; o > 0; o >>= 1) s += __shfl_down_sync(0xffffffffu, s, o);
        if (lane == 0) total = s;
    }
    __syncthreads();
    int i = blockIdx.x * SCAN_B + threadIdx.x;
    if (i < n) {
        int v = g_rowptr[i] + total;
        g_rowptr[i] = v;
        g_cursor[i] = v;
    }
    if (blockIdx.x == 0 && threadIdx.x == 0) g_rowptr[n] = E;
}
__global__ void k_fill(const int* __restrict__ erow, const int* __restrict__ ecol, int E) {
    int e = blockIdx.x * blockDim.x + threadIdx.x;
    if (e < E) {
        int r = erow[e];
        int p = atomicAdd(&g_cursor[r], 1);
        g_cols[p] = ecol[e];
    }
}

// ===========================================================================
// B transpose + fp16 convert: g_Bh[n][k] = half(W[k][n])
// ===========================================================================
__global__ void k_transB(const float* __restrict__ W) {
    int i = blockIdx.x * 256 + threadIdx.x;
    if (i < DD_REL * DD_SRC) {
        int n = i >> 8;
        int k = i & 255;
        g_Bh[i] = __float2half_rn(W[k * DD_REL + n]);
    }
}

// ===========================================================================
// fp16 tensor-core GEMM, A staged via cp.async:
//   C[M,128] = A[M,256] @ Bh^T, fp32 accumulate.
// smem: Bh [128 x 528B] = 67584B | A double buffer 2 x [256 rows x 128B,
//   XOR-swizzled (16B unit ^= row&7)] = 65536B.  Total 133120B.
// 512 threads = 16 warps; warp tile 32x64; BM=256, BK=32 floats; m16n8k16.
// ===========================================================================
#define GEMM_BM 256
#define BROW    528
#define SMA_OFF (128 * BROW)          // 67584: A buffers start here
#define SMEM_SZ (SMA_OFF + 2 * 32768) // 133120

__device__ __forceinline__ uint32_t pack_h2(float x, float y) {
    __half2 h = __floats2half2_rn(x, y);
    return *(uint32_t*)&h;
}
__device__ __forceinline__ uint32_t smem_addr(const void* p) {
    uint32_t a;
    asm("{ .reg .u64 tt; cvta.to.shared.u64 tt, %1; cvt.u32.u64 %0, tt; }" : "=r"(a) : "l"(p));
    return a;
}

__global__ __launch_bounds__(512, 1)
void k_gemm_f16(const float* __restrict__ A, float* __restrict__ C, int M) {
    extern __shared__ char smemc[];
    const int tid  = threadIdx.x;
    const int row0 = blockIdx.x * GEMM_BM;

    // ---- group 0: stage Bh (128 rows x 512B -> 528B-padded rows) ----
    {
        const char* src_base = (const char*)g_Bh;
#pragma unroll
        for (int t = 0; t < 8; t++) {
            int i = tid + t * 512;
            int n = i >> 5;
            int q = i & 31;
            uint32_t dst = smem_addr(smemc + n * BROW + q * 16);
            const char* src = src_base + (size_t)n * 512 + q * 16;
            asm volatile("cp.async.cg.shared.global [%0], [%1], 16;" :: "r"(dst), "l"(src));
        }
        asm volatile("cp.async.commit_group;" ::: "memory");
    }

    // ---- A chunk loader: chunk cc covers k = cc*32 .. cc*32+31 ----
    // 256 rows x 8 16B-units; swizzled dst unit = u ^ (r & 7).
    auto load_a = [&](int cc, int buf) {
#pragma unroll
        for (int t = 0; t < 4; t++) {
            int idx = tid + t * 512;       // 0..2047
            int r = idx >> 3;              // 0..255
            int u = idx & 7;               // 16B unit
            int gr = row0 + r;
            if (gr > M - 1) gr = M - 1;
            const char* src = (const char*)(A + (size_t)gr * DD_SRC + cc * 32 + u * 4);
            uint32_t dst = smem_addr(smemc + SMA_OFF + buf * 32768 + r * 128 + ((u ^ (r & 7)) << 4));
            asm volatile("cp.async.cg.shared.global [%0], [%1], 16;" :: "r"(dst), "l"(src));
        }
        asm volatile("cp.async.commit_group;" ::: "memory");
    };
    load_a(0, 0);
    load_a(1, 1);

    const int warp = tid >> 5;
    const int lane = tid & 31;
    const int gid  = lane >> 2;
    const int tig  = lane & 3;
    const int wm   = warp >> 1;
    const int wn   = warp & 1;

    const int rA = row0 + wm * 32 + gid;
    const int rB = rA + 16;
    const bool okA  = (rA      < M);
    const bool okA8 = (rA + 8  < M);
    const bool okB  = (rB      < M);
    const bool okB8 = (rB + 8  < M);

    // per-lane A smem base: local row = wm*32 + gid (+8i), byte-in-unit = (tig&1)*8
    const char* a_lane = smemc + SMA_OFF + (wm * 32 + gid) * 128 + (tig & 1) * 8;
    const int   xr     = gid & 7;          // xor key (same for all 4 row offsets)
    const char* bbase  = smemc + (wn * 64 + gid) * BROW + tig * 4;

    float c0[8][4], c1[8][4];
#pragma unroll
    for (int nt = 0; nt < 8; nt++)
#pragma unroll
        for (int j = 0; j < 4; j++) { c0[nt][j] = 0.f; c1[nt][j] = 0.f; }

    for (int c = 0; c < 8; c++) {
        // A chunk c lives in commit-group c+1. For c<7 exactly one newer group
        // may remain in flight; for c==7 there is no newer group -> must drain.
        if (c < 7) {
            asm volatile("cp.async.wait_group 1;" ::: "memory");
        } else {
            asm volatile("cp.async.wait_group 0;" ::: "memory");
        }
        __syncthreads();

        const char* ab = a_lane + (c & 1) * 32768;
#pragma unroll
        for (int ks2 = 0; ks2 < 2; ks2++) {
            // 16B-unit indices for lo (cols 2tig) and hi (cols 2tig+8)
            const int ul = (ks2 * 4 + (tig >> 1)) ^ xr;
            const int uh = (ks2 * 4 + (tig >> 1) + 2) ^ xr;

            float2 lo0 = *(const float2*)(ab + 0 * 1024 + ul * 16);
            float2 hi0 = *(const float2*)(ab + 0 * 1024 + uh * 16);
            float2 lo1 = *(const float2*)(ab + 1 * 1024 + ul * 16);
            float2 hi1 = *(const float2*)(ab + 1 * 1024 + uh * 16);
            float2 lo2 = *(const float2*)(ab + 2 * 1024 + ul * 16);
            float2 hi2 = *(const float2*)(ab + 2 * 1024 + uh * 16);
            float2 lo3 = *(const float2*)(ab + 3 * 1024 + ul * 16);
            float2 hi3 = *(const float2*)(ab + 3 * 1024 + uh * 16);

            uint32_t a00 = pack_h2(lo0.x, lo0.y);
            uint32_t a01 = pack_h2(lo1.x, lo1.y);
            uint32_t a02 = pack_h2(hi0.x, hi0.y);
            uint32_t a03 = pack_h2(hi1.x, hi1.y);
            uint32_t a10 = pack_h2(lo2.x, lo2.y);
            uint32_t a11 = pack_h2(lo3.x, lo3.y);
            uint32_t a12 = pack_h2(hi2.x, hi2.y);
            uint32_t a13 = pack_h2(hi3.x, hi3.y);

            const char* bk = bbase + (c * 32 + ks2 * 16) * 2;
#pragma unroll
            for (int nt = 0; nt < 8; nt++) {
                uint32_t b0 = *(const uint32_t*)(bk + nt * (8 * BROW));
                uint32_t b1 = *(const uint32_t*)(bk + nt * (8 * BROW) + 16);
                asm volatile(
                    "mma.sync.aligned.m16n8k16.row.col.f32.f16.f16.f32 "
                    "{%0,%1,%2,%3}, {%4,%5,%6,%7}, {%8,%9}, {%0,%1,%2,%3};\n"
                    : "+f"(c0[nt][0]), "+f"(c0[nt][1]), "+f"(c0[nt][2]), "+f"(c0[nt][3])
                    : "r"(a00), "r"(a01), "r"(a02), "r"(a03), "r"(b0), "r"(b1));
                asm volatile(
                    "mma.sync.aligned.m16n8k16.row.col.f32.f16.f16.f32 "
                    "{%0,%1,%2,%3}, {%4,%5,%6,%7}, {%8,%9}, {%0,%1,%2,%3};\n"
                    : "+f"(c1[nt][0]), "+f"(c1[nt][1]), "+f"(c1[nt][2]), "+f"(c1[nt][3])
                    : "r"(a10), "r"(a11), "r"(a12), "r"(a13), "r"(b0), "r"(b1));
            }
        }

        __syncthreads();
        if (c + 2 < 8) load_a(c + 2, c & 1);
    }

    // ---- store ----
#pragma unroll
    for (int nt = 0; nt < 8; nt++) {
        int col = wn * 64 + nt * 8 + 2 * tig;
        if (okA)  *(float2*)(C + (size_t)rA       * DD_REL + col) = make_float2(c0[nt][0], c0[nt][1]);
        if (okA8) *(float2*)(C + (size_t)(rA + 8) * DD_REL + col) = make_float2(c0[nt][2], c0[nt][3]);
        if (okB)  *(float2*)(C + (size_t)rB       * DD_REL + col) = make_float2(c1[nt][0], c1[nt][1]);
        if (okB8) *(float2*)(C + (size_t)(rB + 8) * DD_REL + col) = make_float2(c1[nt][2], c1[nt][3]);
    }
}

// ===========================================================================
// aggregation: one warp per dst row, float4 per lane, 4-way unrolled gather
// ===========================================================================
__global__ void k_aggregate(const float* __restrict__ src_proj,
                            float* __restrict__ dst_out,
                            float* __restrict__ deg_out,
                            int n_dst) {
    int gwarp = (blockIdx.x * blockDim.x + threadIdx.x) >> 5;
    int lane  = threadIdx.x & 31;
    if (gwarp >= n_dst) return;

    int beg = g_rowptr[gwarp];
    int end = g_rowptr[gwarp + 1];

    const float4* sp = (const float4*)src_proj;
    float4 acc = make_float4(0.f, 0.f, 0.f, 0.f);

    int e = beg;
    for (; e + 4 <= end; e += 4) {
        int c0 = g_cols[e], c1 = g_cols[e + 1], c2 = g_cols[e + 2], c3 = g_cols[e + 3];
        float4 v0 = __ldg(&sp[(size_t)c0 * 32 + lane]);
        float4 v1 = __ldg(&sp[(size_t)c1 * 32 + lane]);
        float4 v2 = __ldg(&sp[(size_t)c2 * 32 + lane]);
        float4 v3 = __ldg(&sp[(size_t)c3 * 32 + lane]);
        acc.x += (v0.x + v1.x) + (v2.x + v3.x);
        acc.y += (v0.y + v1.y) + (v2.y + v3.y);
        acc.z += (v0.z + v1.z) + (v2.z + v3.z);
        acc.w += (v0.w + v1.w) + (v2.w + v3.w);
    }
    for (; e < end; e++) {
        int c0 = g_cols[e];
        float4 v0 = __ldg(&sp[(size_t)c0 * 32 + lane]);
        acc.x += v0.x; acc.y += v0.y; acc.z += v0.z; acc.w += v0.w;
    }

    float d = fmaxf((float)(end - beg), 1.f);
    float inv = 1.f / d;
    acc.x *= inv; acc.y *= inv; acc.z *= inv; acc.w *= inv;

    ((float4*)dst_out)[(size_t)gwarp * 32 + lane] = acc;
    if (lane == 0) deg_out[gwarp] = d;
}

// ===========================================================================
extern "C" void kernel_launch(void* const* d_in, const int* in_sizes, int n_in,
                              void* d_out, int out_size) {
    const float* x_src = (const float*)d_in[0];
    const float* W_src = (const float*)d_in[2];
    const int*   erow  = (const int*)d_in[4];
    const int*   ecol  = (const int*)d_in[5];

    const int N_src = in_sizes[0] / DD_SRC;
    const int N_dst = in_sizes[1] / DD_DST;
    const int E     = in_sizes[4];

    float* out         = (float*)d_out;
    float* dst_out     = out;
    float* srcproj_out = out + (size_t)N_dst * DD_REL;
    float* deg_out     = srcproj_out + (size_t)N_src * DD_REL;

    static cudaStream_t s_csr = nullptr;
    static cudaEvent_t  ev_fork = nullptr, ev_join = nullptr;
    static int init_done = 0;
    if (!init_done) {
        cudaFuncSetAttribute(k_gemm_f16,
                             cudaFuncAttributeMaxDynamicSharedMemorySize, SMEM_SZ);
        cudaStreamCreateWithFlags(&s_csr, cudaStreamNonBlocking);
        cudaEventCreateWithFlags(&ev_fork, cudaEventDisableTiming);
        cudaEventCreateWithFlags(&ev_join, cudaEventDisableTiming);
        init_done = 1;
    }

    cudaEventRecord(ev_fork, 0);
    cudaStreamWaitEvent(s_csr, ev_fork, 0);

    // GEMM stays at submission index 3 (where ncu samples).
    k_zero_deg<<<(N_dst + 255) / 256, 256, 0, s_csr>>>(N_dst);            // idx 0
    k_count<<<(E + 255) / 256, 256, 0, s_csr>>>(erow, E);                 // idx 1
    k_transB<<<(DD_REL * DD_SRC + 255) / 256, 256>>>(W_src);              // idx 2
    int gm_blocks = (N_src + GEMM_BM - 1) / GEMM_BM;
    k_gemm_f16<<<gm_blocks, 512, SMEM_SZ>>>(x_src, srcproj_out, N_src);   // idx 3

    int nb = (N_dst + SCAN_B - 1) / SCAN_B;
    k_scan_partial<<<nb, SCAN_B, 0, s_csr>>>(N_dst);                      // idx 4
    k_scan_add<<<nb, SCAN_B, 0, s_csr>>>(N_dst, E);                       // idx 5
    k_fill<<<(E + 255) / 256, 256, 0, s_csr>>>(erow, ecol, E);            // idx 6
    cudaEventRecord(ev_join, s_csr);
    cudaStreamWaitEvent(0, ev_join, 0);

    // --- aggregation ---
    int agg_blocks = (N_dst + 7) / 8;
    k_aggregate<<<agg_blocks, 256>>>(srcproj_out, dst_out, deg_out, N_dst); // idx 7
}